// round 5
// baseline (speedup 1.0000x reference)
#include <cuda_runtime.h>
#include <cstdint>

#define NTOT 150000
#define CCH 256
#define TM 128
#define TN 64
#define KC 32
#define AS_STRIDE 36   // (4r+4q) -> conflict-light for frag reads (4g+m distinct mod 32)
#define BS_STRIDE 72   // 72 % 32 == 8 -> (8m+g) distinct mod 32 for frag reads

__device__ __forceinline__ uint32_t f2tf32(float f) {
    uint32_t r;
    asm("cvt.rna.tf32.f32 %0, %1;" : "=r"(r) : "f"(f));
    return r;
}

__device__ __forceinline__ void mma_tf32(float c[4], const uint32_t a[4], const uint32_t b[2]) {
    asm volatile("mma.sync.aligned.m16n8k8.row.col.f32.tf32.tf32.f32 "
                 "{%0,%1,%2,%3}, {%4,%5,%6,%7}, {%8,%9}, {%0,%1,%2,%3};"
                 : "+f"(c[0]), "+f"(c[1]), "+f"(c[2]), "+f"(c[3])
                 : "r"(a[0]), "r"(a[1]), "r"(a[2]), "r"(a[3]),
                   "r"(b[0]), "r"(b[1]));
}

__global__ __launch_bounds__(256)
void recon_block_kernel(const float* __restrict__ feats,
                        const float* __restrict__ w1, const float* __restrict__ w2,
                        const float* __restrict__ w3,
                        const float* __restrict__ g1, const float* __restrict__ b1,
                        const float* __restrict__ g2, const float* __restrict__ b2,
                        const float* __restrict__ g3, const float* __restrict__ b3,
                        const int* __restrict__ nx, const int* __restrict__ ny,
                        const int* __restrict__ nz,
                        float* __restrict__ out)
{
    __shared__ uint32_t As[TM * AS_STRIDE];   // 18432 B
    __shared__ uint32_t Bs[KC * BS_STRIDE];   //  9216 B

    const int tid   = threadIdx.x;
    const int lane  = tid & 31;
    const int wid   = tid >> 5;
    const int warpM = wid & 3;    // 4 row-groups of 32
    const int warpN = wid >> 2;   // 2 col-groups of 32
    const int rowBase = blockIdx.y * TM;
    const int colBase = blockIdx.x * TN;

    const float* Wp[3] = {w1, w2, w3};
    const float* Gp[3] = {g1, g2, g3};
    const float* Bp[3] = {b1, b2, b3};
    const int*   Np[3] = {nx, ny, nz};

    // sigmoid accumulator (persists across the 3 axes), same (row,col) map as acc
    float ssum[2][4][4];
#pragma unroll
    for (int mi = 0; mi < 2; mi++)
#pragma unroll
        for (int ni = 0; ni < 4; ni++)
#pragma unroll
            for (int k = 0; k < 4; k++) ssum[mi][ni][k] = 0.f;

    // A loader: thread -> row = tid/8 (+32p), quad = tid%8 (4 floats each)
    const int la_r0 = tid >> 3;
    const int la_q  = tid & 7;
    // B loader: thread -> k-row = tid/16 (+16p), quad = tid%16
    const int lb_k0 = tid >> 4;
    const int lb_q  = tid & 15;

    const float bn_rs = rsqrtf(1.f + 1e-5f);

    for (int axis = 0; axis < 3; axis++) {
        const float* w   = Wp[axis];
        const int*   nbr = Np[axis];

        float acc[2][4][4];
#pragma unroll
        for (int mi = 0; mi < 2; mi++)
#pragma unroll
            for (int ni = 0; ni < 4; ni++)
#pragma unroll
                for (int k = 0; k < 4; k++) acc[mi][ni][k] = 0.f;

        // K = 3 taps * 256 = 768, chunks of 32 (8 chunks per tap; never straddles taps)
        for (int ch = 0; ch < 24; ch++) {
            const int tap = ch >> 3;
            const int ci0 = (ch & 7) * KC;

            __syncthreads();
            // ---- gather A chunk: A[r, kk] = feats[nbr[gr, tap], ci0+kk] (masked) ----
#pragma unroll
            for (int p = 0; p < 4; p++) {
                const int r  = la_r0 + 32 * p;
                const int gr = rowBase + r;
                int nb = -1;
                if (gr < NTOT) nb = nbr[gr * 3 + tap];
                float4 v = make_float4(0.f, 0.f, 0.f, 0.f);
                if (nb >= 0)
                    v = *reinterpret_cast<const float4*>(feats + (size_t)nb * CCH + ci0 + la_q * 4);
                uint32_t* dst = &As[r * AS_STRIDE + la_q * 4];
                dst[0] = f2tf32(v.x); dst[1] = f2tf32(v.y);
                dst[2] = f2tf32(v.z); dst[3] = f2tf32(v.w);
            }
            // ---- load B chunk: B[kk, nn] = w[tap, ci0+kk, colBase+nn] ----
#pragma unroll
            for (int p = 0; p < 2; p++) {
                const int kk = lb_k0 + 16 * p;
                const float4 v = *reinterpret_cast<const float4*>(
                    w + (size_t)tap * CCH * CCH + (size_t)(ci0 + kk) * CCH + colBase + lb_q * 4);
                uint32_t* dst = &Bs[kk * BS_STRIDE + lb_q * 4];
                dst[0] = f2tf32(v.x); dst[1] = f2tf32(v.y);
                dst[2] = f2tf32(v.z); dst[3] = f2tf32(v.w);
            }
            __syncthreads();

            // ---- 4 k-steps of 8 ----
#pragma unroll
            for (int ks = 0; ks < 4; ks++) {
                const int k0 = ks * 8;
                uint32_t a[2][4], b[4][2];
#pragma unroll
                for (int mi = 0; mi < 2; mi++) {
                    const int r0 = warpM * 32 + mi * 16 + (lane >> 2);
                    a[mi][0] = As[r0 * AS_STRIDE + k0 + (lane & 3)];
                    a[mi][1] = As[(r0 + 8) * AS_STRIDE + k0 + (lane & 3)];
                    a[mi][2] = As[r0 * AS_STRIDE + k0 + (lane & 3) + 4];
                    a[mi][3] = As[(r0 + 8) * AS_STRIDE + k0 + (lane & 3) + 4];
                }
#pragma unroll
                for (int ni = 0; ni < 4; ni++) {
                    const int n0 = warpN * 32 + ni * 8 + (lane >> 2);
                    b[ni][0] = Bs[(k0 + (lane & 3)) * BS_STRIDE + n0];
                    b[ni][1] = Bs[(k0 + (lane & 3) + 4) * BS_STRIDE + n0];
                }
#pragma unroll
                for (int mi = 0; mi < 2; mi++)
#pragma unroll
                    for (int ni = 0; ni < 4; ni++)
                        mma_tf32(acc[mi][ni], a[mi], b[ni]);
            }
        }

        // ---- per-axis epilogue: ssum += sigmoid(acc * scale_c + beta_c) ----
        const float* g = Gp[axis];
        const float* b = Bp[axis];
#pragma unroll
        for (int ni = 0; ni < 4; ni++) {
#pragma unroll
            for (int j = 0; j < 2; j++) {
                const int c = colBase + warpN * 32 + ni * 8 + 2 * (lane & 3) + j;
                const float sc = g[c] * bn_rs;
                const float bb = b[c];
#pragma unroll
                for (int mi = 0; mi < 2; mi++)
#pragma unroll
                    for (int h = 0; h < 2; h++) {
                        const float y = acc[mi][ni][2 * h + j] * sc + bb;
                        ssum[mi][ni][2 * h + j] += 1.f / (1.f + __expf(-y));
                    }
            }
        }
    }

    // ---- final: out = ssum * feats ----
#pragma unroll
    for (int mi = 0; mi < 2; mi++) {
#pragma unroll
        for (int h = 0; h < 2; h++) {
            const int gr = rowBase + warpM * 32 + mi * 16 + (lane >> 2) + 8 * h;
            if (gr >= NTOT) continue;
#pragma unroll
            for (int ni = 0; ni < 4; ni++) {
                const int c0 = colBase + warpN * 32 + ni * 8 + 2 * (lane & 3);
                const float2 f = *reinterpret_cast<const float2*>(feats + (size_t)gr * CCH + c0);
                float2 o;
                o.x = ssum[mi][ni][2 * h + 0] * f.x;
                o.y = ssum[mi][ni][2 * h + 1] * f.y;
                *reinterpret_cast<float2*>(out + (size_t)gr * CCH + c0) = o;
            }
        }
    }
}

extern "C" void kernel_launch(void* const* d_in, const int* in_sizes, int n_in,
                              void* d_out, int out_size) {
    (void)in_sizes; (void)n_in; (void)out_size;
    const float* feats = (const float*)d_in[0];
    const float* w1    = (const float*)d_in[1];
    const float* w2    = (const float*)d_in[2];
    const float* w3    = (const float*)d_in[3];
    const float* g1    = (const float*)d_in[4];
    const float* b1    = (const float*)d_in[5];
    const float* g2    = (const float*)d_in[6];
    const float* b2    = (const float*)d_in[7];
    const float* g3    = (const float*)d_in[8];
    const float* b3    = (const float*)d_in[9];
    const int*   nx    = (const int*)d_in[10];
    const int*   ny    = (const int*)d_in[11];
    const int*   nz    = (const int*)d_in[12];
    float* out = (float*)d_out;

    dim3 grid(CCH / TN, (NTOT + TM - 1) / TM);   // (4, 1172)
    recon_block_kernel<<<grid, 256>>>(feats, w1, w2, w3,
                                      g1, b1, g2, b2, g3, b3,
                                      nx, ny, nz, out);
}

// round 7
// speedup vs baseline: 2.5006x; 2.5006x over previous
#include <cuda_runtime.h>
#include <cstdint>

#define NTOT 150000
#define CCH  256
#define TM   128
#define TN   64
#define KC   32
#define ASTR 36   // A smem row stride (words): conflict-free frag reads
#define BSTR 72   // B smem row stride (words): conflict-free frag reads
#define CSTR 65   // Corr row stride (words)

// shared-memory layout (floats)
#define OFF_A 0
#define OFF_B (2 * TM * ASTR)                 // 9216
#define OFF_C (OFF_B + 2 * KC * BSTR)         // 13824
#define OFF_F (OFF_C + TM * CSTR)             // 22144
#define OFF_I (OFF_F + 4 * CCH)               // 23168 (ints start here)
#define SMEM_BYTES (OFF_I * 4 + (2 + 2 * 128 * 2) * 4)   // 94728 B

__device__ __forceinline__ void cpa16(float* dst, const float* src) {
    uint32_t d = (uint32_t)__cvta_generic_to_shared(dst);
    asm volatile("cp.async.ca.shared.global [%0], [%1], 16;" :: "r"(d), "l"(src));
}

__device__ __forceinline__ void mma_tf32(float c[4], const uint32_t a[4], const uint32_t b[2]) {
    asm volatile("mma.sync.aligned.m16n8k8.row.col.f32.tf32.tf32.f32 "
                 "{%0,%1,%2,%3}, {%4,%5,%6,%7}, {%8,%9}, {%0,%1,%2,%3};"
                 : "+f"(c[0]), "+f"(c[1]), "+f"(c[2]), "+f"(c[3])
                 : "r"(a[0]), "r"(a[1]), "r"(a[2]), "r"(a[3]),
                   "r"(b[0]), "r"(b[1]));
}

#define ISSUE_CHUNK(CH, BUF) do {                                              \
    const int ci0_ = (CH) * KC;                                                \
    float* Ad_ = As + (BUF) * TM * ASTR;                                       \
    float* Bd_ = Bs + (BUF) * KC * BSTR;                                       \
    cpa16(Ad_ + (la_r0 +  0) * ASTR + la_q * 4, a_src0 + ci0_);                \
    cpa16(Ad_ + (la_r0 + 32) * ASTR + la_q * 4, a_src1 + ci0_);                \
    cpa16(Ad_ + (la_r0 + 64) * ASTR + la_q * 4, a_src2 + ci0_);                \
    cpa16(Ad_ + (la_r0 + 96) * ASTR + la_q * 4, a_src3 + ci0_);                \
    cpa16(Bd_ + lb_k0 * BSTR + lb_q * 4,                                       \
          wmid + (size_t)(ci0_ + lb_k0) * CCH + colBase + lb_q * 4);           \
    cpa16(Bd_ + (lb_k0 + 16) * BSTR + lb_q * 4,                                \
          wmid + (size_t)(ci0_ + lb_k0 + 16) * CCH + colBase + lb_q * 4);      \
    asm volatile("cp.async.commit_group;" ::: "memory");                       \
} while (0)

__global__ void __launch_bounds__(256, 2)
recon_block_kernel(const float* __restrict__ feats,
                   const float* __restrict__ w1, const float* __restrict__ w2,
                   const float* __restrict__ w3,
                   const float* __restrict__ g1, const float* __restrict__ b1,
                   const float* __restrict__ g2, const float* __restrict__ b2,
                   const float* __restrict__ g3, const float* __restrict__ b3,
                   const int* __restrict__ nx, const int* __restrict__ ny,
                   const int* __restrict__ nz,
                   float* __restrict__ out)
{
    extern __shared__ float sm[];
    float* As   = sm + OFF_A;          // [2][128*36]
    float* Bs   = sm + OFF_B;          // [2][32*72]
    float* Corr = sm + OFF_C;          // [128*65]
    float* Fsm  = sm + OFF_F;          // [4][256]
    int*   sCnt  = (int*)(sm + OFF_I); // [2]
    int2*  sList = (int2*)(sCnt + 2);  // [2][128]

    const int tid   = threadIdx.x;
    const int lane  = tid & 31;
    const int wid   = tid >> 5;
    const int warpM = wid & 3;
    const int warpN = wid >> 2;
    const int rowBase = blockIdx.y * TM;
    const int colBase = blockIdx.x * TN;

    // A loader: row = tid/8 (+32p), quad = tid%8
    const int la_r0 = tid >> 3;
    const int la_q  = tid & 7;
    // B loader: k = tid/16 (+16p), quad = tid%16
    const int lb_k0 = tid >> 4;
    const int lb_q  = tid & 15;

    // per-thread dense-A source pointers (rows clamped for the ragged tail)
    int gr0 = rowBase + la_r0;       if (gr0 >= NTOT) gr0 = NTOT - 1;
    int gr1 = rowBase + la_r0 + 32;  if (gr1 >= NTOT) gr1 = NTOT - 1;
    int gr2 = rowBase + la_r0 + 64;  if (gr2 >= NTOT) gr2 = NTOT - 1;
    int gr3 = rowBase + la_r0 + 96;  if (gr3 >= NTOT) gr3 = NTOT - 1;
    const float* a_src0 = feats + (size_t)gr0 * CCH + la_q * 4;
    const float* a_src1 = feats + (size_t)gr1 * CCH + la_q * 4;
    const float* a_src2 = feats + (size_t)gr2 * CCH + la_q * 4;
    const float* a_src3 = feats + (size_t)gr3 * CCH + la_q * 4;

    const float* Wp[3] = {w1, w2, w3};
    const float* Gp[3] = {g1, g2, g3};
    const float* Bp[3] = {b1, b2, b3};
    const int*   Np[3] = {nx, ny, nz};

    const float bn_rs = rsqrtf(1.f + 1e-5f);

    float ssum[2][4][4];
#pragma unroll
    for (int mi = 0; mi < 2; mi++)
#pragma unroll
        for (int ni = 0; ni < 4; ni++)
#pragma unroll
            for (int k = 0; k < 4; k++) ssum[mi][ni][k] = 0.f;

    for (int axis = 0; axis < 3; axis++) {
        const float* w    = Wp[axis];
        const float* wmid = w + (size_t)CCH * CCH;   // identity tap (offset 0)
        const int*   nbr  = Np[axis];

        __syncthreads();   // previous axis fully done with As/Bs/Corr

        // zero Corr, reset counters
        for (int i = tid; i < TM * CSTR; i += 256) Corr[i] = 0.f;
        if (tid < 2) sCnt[tid] = 0;
        __syncthreads();

        // build sparse-correction lists: taps -1 (col 0) and +1 (col 2)
        {
            const int r   = tid & 127;
            const int tsl = tid >> 7;          // 0 -> tap -1, 1 -> tap +1
            const int gr  = rowBase + r;
            if (gr < NTOT) {
                const int nb = nbr[gr * 3 + tsl * 2];
                if (nb >= 0) {
                    const int ix = atomicAdd(&sCnt[tsl], 1);
                    sList[tsl * 128 + ix] = make_int2(r, nb);
                }
            }
        }

        // prologue: async loads for dense chunks 0 and 1 (overlap with corrections)
        ISSUE_CHUNK(0, 0);
        ISSUE_CHUNK(1, 1);

        __syncthreads();   // Corr zeroed + lists visible

        // ---- sparse corrections: Corr[r,:] += feats[nb,:] @ W[tap][:, colTile] ----
        for (int tsl = 0; tsl < 2; tsl++) {
            const int cnt = sCnt[tsl];
            const float* wt = w + (size_t)(tsl * 2) * CCH * CCH;
            for (int base = 0; base < cnt; base += 4) {
#pragma unroll
                for (int e = 0; e < 4; e++) {
                    float v = 0.f;
                    if (base + e < cnt)
                        v = feats[(size_t)sList[tsl * 128 + base + e].y * CCH + tid];
                    Fsm[e * CCH + tid] = v;
                }
                __syncthreads();
                const int j  = tid & 63;
                const int ks = tid >> 6;
                float part0 = 0.f, part1 = 0.f, part2 = 0.f, part3 = 0.f;
                const float* wp = wt + colBase + j;
#pragma unroll 8
                for (int k = ks * 64; k < ks * 64 + 64; k++) {
                    const float wv = wp[(size_t)k * CCH];
                    part0 += Fsm[0 * CCH + k] * wv;
                    part1 += Fsm[1 * CCH + k] * wv;
                    part2 += Fsm[2 * CCH + k] * wv;
                    part3 += Fsm[3 * CCH + k] * wv;
                }
                if (base + 0 < cnt) atomicAdd(&Corr[sList[tsl * 128 + base + 0].x * CSTR + j], part0);
                if (base + 1 < cnt) atomicAdd(&Corr[sList[tsl * 128 + base + 1].x * CSTR + j], part1);
                if (base + 2 < cnt) atomicAdd(&Corr[sList[tsl * 128 + base + 2].x * CSTR + j], part2);
                if (base + 3 < cnt) atomicAdd(&Corr[sList[tsl * 128 + base + 3].x * CSTR + j], part3);
                __syncthreads();
            }
        }

        // ---- dense identity GEMM: acc = F[rows,:] @ W[1][:, colTile], K=256 ----
        float acc[2][4][4];
#pragma unroll
        for (int mi = 0; mi < 2; mi++)
#pragma unroll
            for (int ni = 0; ni < 4; ni++)
#pragma unroll
                for (int k = 0; k < 4; k++) acc[mi][ni][k] = 0.f;

#pragma unroll
        for (int ch = 0; ch < 8; ch++) {
            if (ch < 7) asm volatile("cp.async.wait_group 1;" ::: "memory");
            else        asm volatile("cp.async.wait_group 0;" ::: "memory");
            __syncthreads();

            const float* Ab = As + (ch & 1) * TM * ASTR;
            const float* Bb = Bs + (ch & 1) * KC * BSTR;

#pragma unroll
            for (int kst = 0; kst < 4; kst++) {
                const int k0 = kst * 8;
                uint32_t a[2][4], b[4][2];
#pragma unroll
                for (int mi = 0; mi < 2; mi++) {
                    const int r0 = warpM * 32 + mi * 16 + (lane >> 2);
                    a[mi][0] = __float_as_uint(Ab[r0 * ASTR + k0 + (lane & 3)]);
                    a[mi][1] = __float_as_uint(Ab[(r0 + 8) * ASTR + k0 + (lane & 3)]);
                    a[mi][2] = __float_as_uint(Ab[r0 * ASTR + k0 + (lane & 3) + 4]);
                    a[mi][3] = __float_as_uint(Ab[(r0 + 8) * ASTR + k0 + (lane & 3) + 4]);
                }
#pragma unroll
                for (int ni = 0; ni < 4; ni++) {
                    const int n0 = warpN * 32 + ni * 8 + (lane >> 2);
                    b[ni][0] = __float_as_uint(Bb[(k0 + (lane & 3)) * BSTR + n0]);
                    b[ni][1] = __float_as_uint(Bb[(k0 + (lane & 3) + 4) * BSTR + n0]);
                }
#pragma unroll
                for (int mi = 0; mi < 2; mi++)
#pragma unroll
                    for (int ni = 0; ni < 4; ni++)
                        mma_tf32(acc[mi][ni], a[mi], b[ni]);
            }
            __syncthreads();
            if (ch + 2 < 8) { ISSUE_CHUNK(ch + 2, ch & 1); }
        }

        // ---- epilogue: ssum += sigmoid((dense + Corr) * scale + beta) ----
        const float* g = Gp[axis];
        const float* b = Bp[axis];
#pragma unroll
        for (int ni = 0; ni < 4; ni++) {
#pragma unroll
            for (int j = 0; j < 2; j++) {
                const int cl = warpN * 32 + ni * 8 + 2 * (lane & 3) + j;
                const float sc = g[colBase + cl] * bn_rs;
                const float bb = b[colBase + cl];
#pragma unroll
                for (int mi = 0; mi < 2; mi++)
#pragma unroll
                    for (int h = 0; h < 2; h++) {
                        const int rl = warpM * 32 + mi * 16 + (lane >> 2) + 8 * h;
                        const float y = (acc[mi][ni][2 * h + j] + Corr[rl * CSTR + cl]) * sc + bb;
                        ssum[mi][ni][2 * h + j] += 1.f / (1.f + __expf(-y));
                    }
            }
        }
    }

    // ---- final: out = ssum * feats ----
#pragma unroll
    for (int mi = 0; mi < 2; mi++) {
#pragma unroll
        for (int h = 0; h < 2; h++) {
            const int gr = rowBase + warpM * 32 + mi * 16 + (lane >> 2) + 8 * h;
            if (gr >= NTOT) continue;
#pragma unroll
            for (int ni = 0; ni < 4; ni++) {
                const int c0 = colBase + warpN * 32 + ni * 8 + 2 * (lane & 3);
                const float2 f = *reinterpret_cast<const float2*>(feats + (size_t)gr * CCH + c0);
                float2 o;
                o.x = ssum[mi][ni][2 * h + 0] * f.x;
                o.y = ssum[mi][ni][2 * h + 1] * f.y;
                *reinterpret_cast<float2*>(out + (size_t)gr * CCH + c0) = o;
            }
        }
    }
}

extern "C" void kernel_launch(void* const* d_in, const int* in_sizes, int n_in,
                              void* d_out, int out_size) {
    (void)in_sizes; (void)n_in; (void)out_size;
    const float* feats = (const float*)d_in[0];
    const float* w1    = (const float*)d_in[1];
    const float* w2    = (const float*)d_in[2];
    const float* w3    = (const float*)d_in[3];
    const float* g1    = (const float*)d_in[4];
    const float* b1    = (const float*)d_in[5];
    const float* g2    = (const float*)d_in[6];
    const float* b2    = (const float*)d_in[7];
    const float* g3    = (const float*)d_in[8];
    const float* b3    = (const float*)d_in[9];
    const int*   nx    = (const int*)d_in[10];
    const int*   ny    = (const int*)d_in[11];
    const int*   nz    = (const int*)d_in[12];
    float* out = (float*)d_out;

    cudaFuncSetAttribute(recon_block_kernel,
                         cudaFuncAttributeMaxDynamicSharedMemorySize, SMEM_BYTES);

    dim3 grid(CCH / TN, (NTOT + TM - 1) / TM);   // (4, 1172)
    recon_block_kernel<<<grid, 256, SMEM_BYTES>>>(feats, w1, w2, w3,
                                                  g1, b1, g2, b2, g3, b3,
                                                  nx, ny, nz, out);
}

// round 12
// speedup vs baseline: 2.5611x; 1.0242x over previous
#include <cuda_runtime.h>
#include <cstdint>

#define NTOT 150000
#define CCH  256
#define TM   128
#define TN   64
#define KC   16
#define ASTR 20    // A row stride (words): 20*r mod 32 hits multiples of 4 -> +k(0..3) conflict-free
#define BSTR 72    // B row stride: 72 mod 32 = 8 -> 8k + n0 conflict-free
#define CSTR 65
#define AROWS 160  // 128 dense + 16 tap- + 16 tap+

#define OFF_A 0
#define OFF_B (2 * AROWS * ASTR)               // 6400
#define OFF_C (OFF_B + 2 * 3 * KC * BSTR)      // 13312
#define OFF_CNT (OFF_C + TM * CSTR)            // 21632
#define OFF_LR  (OFF_CNT + 2)
#define OFF_LN  (OFF_LR + 256)
#define SMEM_WORDS (OFF_LN + 256)              // 22146
#define SMEM_BYTES (SMEM_WORDS * 4)            // 88584 B -> 2 CTAs/SM

__device__ __forceinline__ void cpa16(float* dst, const float* src) {
    uint32_t d = (uint32_t)__cvta_generic_to_shared(dst);
    asm volatile("cp.async.ca.shared.global [%0], [%1], 16;" :: "r"(d), "l"(src));
}
// src-size form: copies sb bytes (0 or 16), zero-fills the rest of the 16B
__device__ __forceinline__ void cpa16z(float* dst, const float* src, int sb) {
    uint32_t d = (uint32_t)__cvta_generic_to_shared(dst);
    asm volatile("cp.async.ca.shared.global [%0], [%1], 16, %2;" :: "r"(d), "l"(src), "r"(sb));
}

__device__ __forceinline__ void mma_tf32(float c[4], const uint32_t a[4], const uint32_t b[2]) {
    asm volatile("mma.sync.aligned.m16n8k8.row.col.f32.tf32.tf32.f32 "
                 "{%0,%1,%2,%3}, {%4,%5,%6,%7}, {%8,%9}, {%0,%1,%2,%3};"
                 : "+f"(c[0]), "+f"(c[1]), "+f"(c[2]), "+f"(c[3])
                 : "r"(a[0]), "r"(a[1]), "r"(a[2]), "r"(a[3]),
                   "r"(b[0]), "r"(b[1]));
}

__global__ void __launch_bounds__(256, 2)
recon_block_kernel(const float* __restrict__ feats,
                   const float* __restrict__ w1, const float* __restrict__ w2,
                   const float* __restrict__ w3,
                   const float* __restrict__ g1, const float* __restrict__ b1,
                   const float* __restrict__ g2, const float* __restrict__ b2,
                   const float* __restrict__ g3, const float* __restrict__ b3,
                   const int* __restrict__ nx, const int* __restrict__ ny,
                   const int* __restrict__ nz,
                   float* __restrict__ out)
{
    extern __shared__ float sm[];
    float* As   = sm + OFF_A;            // [2][160*20]
    float* Bs   = sm + OFF_B;            // [2][3][16*72]  slot0=mid, 1=tap-, 2=tap+
    float* Corr = sm + OFF_C;            // [128*65]
    int*   sCnt  = (int*)(sm + OFF_CNT); // [2]
    int*   listR = (int*)(sm + OFF_LR);  // [2][128]
    int*   listN = (int*)(sm + OFF_LN);  // [2][128]

    const int tid   = threadIdx.x;
    const int lane  = tid & 31;
    const int wid   = tid >> 5;
    const int warpM = wid & 3;
    const int warpN = wid >> 2;
    const int extTap = wid & 1;          // this warp's correction tap
    const int extN0  = (wid >> 1) * 16;  // this warp's 16-col slab for corrections
    const int rowBase = blockIdx.y * TM;
    const int colBase = blockIdx.x * TN;

    // dense A loader: row = tid>>2 (+64), quad = tid&3
    const int la_r  = tid >> 2;
    const int la_q4 = (tid & 3) * 4;
    int gA0 = rowBase + la_r;      if (gA0 >= NTOT) gA0 = NTOT - 1;
    int gA1 = rowBase + la_r + 64; if (gA1 >= NTOT) gA1 = NTOT - 1;
    const float* aS0 = feats + (size_t)gA0 * CCH + la_q4;
    const float* aS1 = feats + (size_t)gA1 * CCH + la_q4;

    // B loader: k-row = tid>>4, quad = tid&15
    const int lb_k  = tid >> 4;
    const int lb_q4 = (tid & 15) * 4;

    const float bn_rs = rsqrtf(1.f + 1e-5f);

    float ssum[2][4][4];
#pragma unroll
    for (int mi = 0; mi < 2; mi++)
#pragma unroll
        for (int ni = 0; ni < 4; ni++)
#pragma unroll
            for (int k = 0; k < 4; k++) ssum[mi][ni][k] = 0.f;

#pragma unroll
    for (int axis = 0; axis < 3; axis++) {
        const float* w   = axis == 0 ? w1 : axis == 1 ? w2 : w3;
        const float* gam = axis == 0 ? g1 : axis == 1 ? g2 : g3;
        const float* bet = axis == 0 ? b1 : axis == 1 ? b2 : b3;
        const int*   nbr = axis == 0 ? nx : axis == 1 ? ny : nz;
        const float* wb0 = w + (size_t)CCH * CCH + colBase;      // mid tap
        const float* wb1 = w + colBase;                          // tap -1
        const float* wb2 = w + (size_t)2 * CCH * CCH + colBase;  // tap +1

        __syncthreads();   // previous axis done with Corr / lists
        for (int i = tid; i < TM * CSTR; i += 256) Corr[i] = 0.f;
        if (tid < 2) sCnt[tid] = 0;
        __syncthreads();

        // build correction lists (tap- : t=0, tap+ : t=1)
        {
            const int r  = tid & 127;
            const int t  = tid >> 7;
            const int gr = rowBase + r;
            if (gr < NTOT) {
                const int nb = nbr[gr * 3 + t * 2];
                if (nb >= 0) {
                    const int ix = atomicAdd(&sCnt[t], 1);
                    listR[t * 128 + ix] = r;
                    listN[t * 128 + ix] = nb;
                }
            }
        }
        __syncthreads();

        // ext-A loader setup: threads 0..127 cover 32 ext rows x 4 quads
        const float* eSrc = feats;
        int eBytes = 0;
        if (tid < 128) {
            const int er  = tid >> 2;        // 0..31
            const int t   = er >> 4;
            const int idx = er & 15;
            if (idx < sCnt[t]) {
                eSrc = feats + (size_t)listN[t * 128 + idx] * CCH + la_q4;
                eBytes = 16;
            }
        }

#define ISSUE(CH, BUF) do {                                                    \
        const int ci0_ = (CH) * KC;                                            \
        float* Ad_ = As + (BUF) * (AROWS * ASTR);                              \
        float* Bd_ = Bs + (BUF) * (3 * KC * BSTR);                             \
        cpa16(Ad_ + la_r * ASTR + la_q4, aS0 + ci0_);                          \
        cpa16(Ad_ + (la_r + 64) * ASTR + la_q4, aS1 + ci0_);                   \
        if (tid < 128)                                                         \
            cpa16z(Ad_ + (128 + (tid >> 2)) * ASTR + la_q4, eSrc + ci0_, eBytes); \
        cpa16(Bd_ + 0 * KC * BSTR + lb_k * BSTR + lb_q4,                       \
              wb0 + (size_t)(ci0_ + lb_k) * CCH + lb_q4);                      \
        cpa16(Bd_ + 1 * KC * BSTR + lb_k * BSTR + lb_q4,                       \
              wb1 + (size_t)(ci0_ + lb_k) * CCH + lb_q4);                      \
        cpa16(Bd_ + 2 * KC * BSTR + lb_k * BSTR + lb_q4,                       \
              wb2 + (size_t)(ci0_ + lb_k) * CCH + lb_q4);                      \
        asm volatile("cp.async.commit_group;" ::: "memory");                   \
    } while (0)

        ISSUE(0, 0);
        ISSUE(1, 1);

        float acc[2][4][4];
        float aex[2][4];
#pragma unroll
        for (int mi = 0; mi < 2; mi++)
#pragma unroll
            for (int ni = 0; ni < 4; ni++)
#pragma unroll
                for (int k = 0; k < 4; k++) acc[mi][ni][k] = 0.f;
#pragma unroll
        for (int e = 0; e < 2; e++)
#pragma unroll
            for (int k = 0; k < 4; k++) aex[e][k] = 0.f;

#pragma unroll 2
        for (int ch = 0; ch < 16; ch++) {
            if (ch < 15) asm volatile("cp.async.wait_group 1;" ::: "memory");
            else         asm volatile("cp.async.wait_group 0;" ::: "memory");
            __syncthreads();

            const float* Ab = As + (ch & 1) * (AROWS * ASTR);
            const float* Bm = Bs + (ch & 1) * (3 * KC * BSTR);        // mid tile
            const float* Bt = Bm + (1 + extTap) * KC * BSTR;          // this warp's tap tile

#pragma unroll
            for (int kst = 0; kst < 2; kst++) {
                const int kq = kst * 8 + (lane & 3);
                uint32_t a[2][4], b[4][2];
#pragma unroll
                for (int mi = 0; mi < 2; mi++) {
                    const int r0 = warpM * 32 + mi * 16 + (lane >> 2);
                    a[mi][0] = __float_as_uint(Ab[r0 * ASTR + kq]);
                    a[mi][1] = __float_as_uint(Ab[(r0 + 8) * ASTR + kq]);
                    a[mi][2] = __float_as_uint(Ab[r0 * ASTR + kq + 4]);
                    a[mi][3] = __float_as_uint(Ab[(r0 + 8) * ASTR + kq + 4]);
                }
#pragma unroll
                for (int ni = 0; ni < 4; ni++) {
                    const int n0 = warpN * 32 + ni * 8 + (lane >> 2);
                    b[ni][0] = __float_as_uint(Bm[kq * BSTR + n0]);
                    b[ni][1] = __float_as_uint(Bm[(kq + 4) * BSTR + n0]);
                }
#pragma unroll
                for (int mi = 0; mi < 2; mi++)
#pragma unroll
                    for (int ni = 0; ni < 4; ni++)
                        mma_tf32(acc[mi][ni], a[mi], b[ni]);

                // correction rows: one m16 tile per tap, 16-col slab per warp
                {
                    const int er0 = 128 + 16 * extTap + (lane >> 2);
                    uint32_t ea[4], eb[2][2];
                    ea[0] = __float_as_uint(Ab[er0 * ASTR + kq]);
                    ea[1] = __float_as_uint(Ab[(er0 + 8) * ASTR + kq]);
                    ea[2] = __float_as_uint(Ab[er0 * ASTR + kq + 4]);
                    ea[3] = __float_as_uint(Ab[(er0 + 8) * ASTR + kq + 4]);
#pragma unroll
                    for (int e = 0; e < 2; e++) {
                        const int n0e = extN0 + e * 8 + (lane >> 2);
                        eb[e][0] = __float_as_uint(Bt[kq * BSTR + n0e]);
                        eb[e][1] = __float_as_uint(Bt[(kq + 4) * BSTR + n0e]);
                    }
                    mma_tf32(aex[0], ea, eb[0]);
                    mma_tf32(aex[1], ea, eb[1]);
                }
            }
            __syncthreads();
            if (ch + 2 < 16) ISSUE(ch + 2, ch & 1);
        }
#undef ISSUE

        // scatter correction accumulators into Corr
        {
            const int cnt_t = sCnt[extTap];
#pragma unroll
            for (int h = 0; h < 2; h++) {
                const int idx = (lane >> 2) + 8 * h;
                if (idx < cnt_t && idx < 16) {
                    const int r = listR[extTap * 128 + idx];
#pragma unroll
                    for (int e = 0; e < 2; e++)
#pragma unroll
                        for (int j = 0; j < 2; j++)
                            atomicAdd(&Corr[r * CSTR + extN0 + e * 8 + 2 * (lane & 3) + j],
                                      aex[e][2 * h + j]);
                }
            }
        }
        // overflow fallback (cnt > 16 per tap): essentially never runs, kept for correctness
        for (int t = 0; t < 2; t++) {
            const int c = sCnt[t];
            for (int idx = 16; idx < c; idx++) {
                if (tid < 64) {
                    const float* fr = feats + (size_t)listN[t * 128 + idx] * CCH;
                    const float* wp = (t == 0 ? w : w + (size_t)2 * CCH * CCH) + colBase + tid;
                    float s = 0.f;
                    for (int k = 0; k < CCH; k++) s += fr[k] * wp[(size_t)k * CCH];
                    atomicAdd(&Corr[listR[t * 128 + idx] * CSTR + tid], s);
                }
            }
        }
        __syncthreads();

        // epilogue: ssum += sigmoid((dense + Corr) * scale + beta)
#pragma unroll
        for (int ni = 0; ni < 4; ni++) {
#pragma unroll
            for (int j = 0; j < 2; j++) {
                const int cl = warpN * 32 + ni * 8 + 2 * (lane & 3) + j;
                const float sc = gam[colBase + cl] * bn_rs;
                const float bb = bet[colBase + cl];
#pragma unroll
                for (int mi = 0; mi < 2; mi++)
#pragma unroll
                    for (int h = 0; h < 2; h++) {
                        const int rl = warpM * 32 + mi * 16 + (lane >> 2) + 8 * h;
                        const float y = (acc[mi][ni][2 * h + j] + Corr[rl * CSTR + cl]) * sc + bb;
                        ssum[mi][ni][2 * h + j] += 1.f / (1.f + __expf(-y));
                    }
            }
        }
    }

    // final: out = ssum * feats
#pragma unroll
    for (int mi = 0; mi < 2; mi++) {
#pragma unroll
        for (int h = 0; h < 2; h++) {
            const int gr = rowBase + warpM * 32 + mi * 16 + (lane >> 2) + 8 * h;
            if (gr >= NTOT) continue;
#pragma unroll
            for (int ni = 0; ni < 4; ni++) {
                const int c0 = colBase + warpN * 32 + ni * 8 + 2 * (lane & 3);
                const float2 f = *reinterpret_cast<const float2*>(feats + (size_t)gr * CCH + c0);
                float2 o;
                o.x = ssum[mi][ni][2 * h + 0] * f.x;
                o.y = ssum[mi][ni][2 * h + 1] * f.y;
                *reinterpret_cast<float2*>(out + (size_t)gr * CCH + c0) = o;
            }
        }
    }
}

extern "C" void kernel_launch(void* const* d_in, const int* in_sizes, int n_in,
                              void* d_out, int out_size) {
    (void)in_sizes; (void)n_in; (void)out_size;
    const float* feats = (const float*)d_in[0];
    const float* w1    = (const float*)d_in[1];
    const float* w2    = (const float*)d_in[2];
    const float* w3    = (const float*)d_in[3];
    const float* g1    = (const float*)d_in[4];
    const float* b1    = (const float*)d_in[5];
    const float* g2    = (const float*)d_in[6];
    const float* b2    = (const float*)d_in[7];
    const float* g3    = (const float*)d_in[8];
    const float* b3    = (const float*)d_in[9];
    const int*   nx    = (const int*)d_in[10];
    const int*   ny    = (const int*)d_in[11];
    const int*   nz    = (const int*)d_in[12];
    float* out = (float*)d_out;

    cudaFuncSetAttribute(recon_block_kernel,
                         cudaFuncAttributeMaxDynamicSharedMemorySize, SMEM_BYTES);

    dim3 grid(CCH / TN, (NTOT + TM - 1) / TM);   // (4, 1172)
    recon_block_kernel<<<grid, 256, SMEM_BYTES>>>(feats, w1, w2, w3,
                                                  g1, b1, g2, b2, g3, b3,
                                                  nx, ny, nz, out);
}